// round 5
// baseline (speedup 1.0000x reference)
#include <cuda_runtime.h>
#include <cuda_fp16.h>

// SDFGrid: trilinear-interpolated grid normals + relu(-grid) gather.
//
// R5 changes:
//  - precompute: 2 bricks (16 nodes, z-quad x x-pair x y-pair) per thread;
//    12 float4 loads + 8 edge scalars, 8 contiguous STG.128 (one full 128B
//    line of the table per thread).
//  - gather: __ldcs on pixel streams, __stcs on output, so streaming data is
//    evict-first in L2 and the 134MB table keeps residency.

#define GRID_R   256
#define NVOX     (GRID_R * GRID_R * GRID_R)

// Brick-swizzled: node (x,y,z) -> uint2 index
//   brick = ((x>>1)*128 + (y>>1))*128 + (z>>1)
//   idx   = brick*8 + (x&1)*4 + (y&1)*2 + (z&1)
static __device__ uint2 g_table[NVOX];

__device__ __forceinline__ unsigned int packh2(float a, float b) {
    __half2 h = __floats2half2_rn(a, b);
    return *reinterpret_cast<unsigned int*>(&h);
}

// float4 index of the z-quad q of row (x, y)
__device__ __forceinline__ int rowf4(int x, int y, int q) {
    return ((x << 8) + y) * 64 + q;
}

// One thread = one z-quad of an (x-pair, y-pair) column = 2 bricks = 128 B out.
__global__ void __launch_bounds__(256)
precompute_normals_kernel(const float* __restrict__ g) {
    int tid = blockIdx.x * blockDim.x + threadIdx.x;   // NVOX/16 threads
    int q  = tid & 63;
    int by = (tid >> 6) & 127;
    int bx = tid >> 13;

    int x0 = bx << 1, x1 = x0 + 1;
    int y0 = by << 1, y1 = y0 + 1;

    const float4* __restrict__ g4 = (const float4*)g;

    float4 c00 = __ldg(g4 + rowf4(x0, y0, q));
    float4 c01 = __ldg(g4 + rowf4(x0, y1, q));
    float4 c10 = __ldg(g4 + rowf4(x1, y0, q));
    float4 c11 = __ldg(g4 + rowf4(x1, y1, q));

    // ---- z edge scalars (clamped addresses at borders; values unused there) ----
    bool zlo = (q == 0), zhi = (q == 63);
    int dm = zlo ? 0 : -1;
    int dp = zhi ? 3 : 4;
    int e00 = rowf4(x0, y0, q) * 4, e01 = rowf4(x0, y1, q) * 4;
    int e10 = rowf4(x1, y0, q) * 4, e11 = rowf4(x1, y1, q) * 4;
    float zm00 = __ldg(g + e00 + dm), zp00 = __ldg(g + e00 + dp);
    float zm01 = __ldg(g + e01 + dm), zp01 = __ldg(g + e01 + dp);
    float zm10 = __ldg(g + e10 + dm), zp10 = __ldg(g + e10 + dp);
    float zm11 = __ldg(g + e11 + dm), zp11 = __ldg(g + e11 + dp);

    // ---- y neighbor rows ----
    bool ylo = (by == 0), yhi = (by == 127);
    int ym = ylo ? y0 : y0 - 1;
    int yp = yhi ? y1 : y1 + 1;
    float4 m0 = __ldg(g4 + rowf4(x0, ym, q));
    float4 m1 = __ldg(g4 + rowf4(x1, ym, q));
    float4 p0 = __ldg(g4 + rowf4(x0, yp, q));
    float4 p1 = __ldg(g4 + rowf4(x1, yp, q));

    // ---- x neighbor rows ----
    bool xlo = (bx == 0), xhi = (bx == 127);
    int xm = xlo ? x0 : x0 - 1;
    int xp = xhi ? x1 : x1 + 1;
    float4 a0 = __ldg(g4 + rowf4(xm, y0, q));
    float4 a1 = __ldg(g4 + rowf4(xm, y1, q));
    float4 b0 = __ldg(g4 + rowf4(xp, y0, q));
    float4 b1 = __ldg(g4 + rowf4(xp, y1, q));

    const float S = 255.0f / 8.0f;   // 1/(2*VS)

    int brick0 = (((bx << 7) | by) << 7) | (q << 1);
    uint2* __restrict__ dst = g_table + ((long long)brick0 << 3);

    // Per (ox, oy) node column: compute 4 z-derivs, y-derivs, x-derivs, pack.
#define GET(v, k) ((k) == 0 ? (v).x : (k) == 1 ? (v).y : (k) == 2 ? (v).z : (v).w)

#define EMIT(OX, OY, C, ZM, ZP, YC0, YC1, YM, YP, XC0, XC1, XA, XB, ISY1, ISX1)     \
    {                                                                               \
        float dzv[4];                                                               \
        dzv[0] = zlo ? ((C).y - 1.5f * (C).x + 0.5f * (C).z) : ((C).y - (ZM));      \
        dzv[1] = (C).z - (C).x;                                                     \
        dzv[2] = (C).w - (C).y;                                                     \
        dzv[3] = zhi ? (1.5f * (C).w - (C).z - 0.5f * (C).y) : ((ZP) - (C).z);      \
        _Pragma("unroll")                                                           \
        for (int k = 0; k < 4; k++) {                                               \
            float yc0 = GET(YC0, k), yc1 = GET(YC1, k);                             \
            float ymv = GET(YM, k),  ypv = GET(YP, k);                              \
            float dy = (ISY1)                                                       \
                ? (yhi ? (1.5f * yc1 - yc0 - 0.5f * ymv) : (ypv - yc0))             \
                : (ylo ? (yc1 - 1.5f * yc0 + 0.5f * ypv) : (yc1 - ymv));            \
            float xc0 = GET(XC0, k), xc1 = GET(XC1, k);                             \
            float xav = GET(XA, k),  xbv = GET(XB, k);                              \
            float dx = (ISX1)                                                       \
                ? (xhi ? (1.5f * xc1 - xc0 - 0.5f * xav) : (xbv - xc0))             \
                : (xlo ? (xc1 - 1.5f * xc0 + 0.5f * xbv) : (xc1 - xav));            \
            float cval = GET(C, k);                                                 \
            uint2 e;                                                                \
            e.x = packh2(dx * S, dy * S);                                           \
            e.y = packh2(dzv[k] * S, fmaxf(-cval, 0.0f));                           \
            tmp[k] = e;                                                             \
        }                                                                           \
        int o = ((OX) << 2) + ((OY) << 1);                                          \
        *reinterpret_cast<uint4*>(dst + o)     = *reinterpret_cast<uint4*>(&tmp[0]);\
        *reinterpret_cast<uint4*>(dst + 8 + o) = *reinterpret_cast<uint4*>(&tmp[2]);\
    }

    uint2 tmp[4];
    //    ox oy  C    zm    zp    yC0  yC1  yM  yP  xC0  xC1  xA  xB  y1? x1?
    EMIT(0, 0, c00, zm00, zp00, c00, c01, m0, p0, c00, c10, a0, b0, 0, 0)
    EMIT(0, 1, c01, zm01, zp01, c00, c01, m0, p0, c01, c11, a1, b1, 1, 0)
    EMIT(1, 0, c10, zm10, zp10, c10, c11, m1, p1, c00, c10, a0, b0, 0, 1)
    EMIT(1, 1, c11, zm11, zp11, c10, c11, m1, p1, c01, c11, a1, b1, 1, 1)
#undef EMIT
#undef GET
}

__device__ __forceinline__ void corner_acc(uint2 v, float w,
                                           float& ax, float& ay, float& az) {
    __half2 h_xy = *reinterpret_cast<__half2*>(&v.x);
    __half2 h_zw = *reinterpret_cast<__half2*>(&v.y);
    float2 xy = __half22float2(h_xy);
    float2 zw = __half22float2(h_zw);
    ax = fmaf(w, xy.x, ax);
    ay = fmaf(w, xy.y, ay);
    az = fmaf(w, zw.x, az);
}

__global__ void __launch_bounds__(256)
gather_kernel(const int* __restrict__ vidx,
              const float* __restrict__ pos,
              const int* __restrict__ mask,
              float4* __restrict__ out,
              int npix) {
    int p = blockIdx.x * blockDim.x + threadIdx.x;
    if (p >= npix) return;

    const float BB_MIN_F = -2.0f;
    const float VS = 4.0f / 255.0f;

    // Streaming inputs: evict-first so the table keeps L2.
    int x = __ldcs(vidx + 3 * p + 0);
    int y = __ldcs(vidx + 3 * p + 1);
    int z = __ldcs(vidx + 3 * p + 2);

    float px = __ldcs(pos + 3 * p + 0);
    float py = __ldcs(pos + 3 * p + 1);
    float pz = __ldcs(pos + 3 * p + 2);

    float m = (float)__ldcs(mask + p);

    float tx = (px - (BB_MIN_F + (float)x * VS)) / VS;
    float ty = (py - (BB_MIN_F + (float)y * VS)) / VS;
    float tz = (pz - (BB_MIN_F + (float)z * VS)) / VS;

    int xp0 = ((x >> 1) << 17)       + ((x & 1) << 2);
    int xp1 = (((x + 1) >> 1) << 17) + (((x + 1) & 1) << 2);
    int yp0 = ((y >> 1) << 10)       + ((y & 1) << 1);
    int yp1 = (((y + 1) >> 1) << 10) + (((y + 1) & 1) << 1);
    int zp0 = ((z >> 1) << 3)        + (z & 1);
    int zp1 = (((z + 1) >> 1) << 3)  + ((z + 1) & 1);

    const uint2* __restrict__ T = g_table;

    uint2 c000 = __ldg(T + xp0 + yp0 + zp0);
    uint2 c001 = __ldg(T + xp0 + yp0 + zp1);
    uint2 c010 = __ldg(T + xp0 + yp1 + zp0);
    uint2 c011 = __ldg(T + xp0 + yp1 + zp1);
    uint2 c100 = __ldg(T + xp1 + yp0 + zp0);
    uint2 c101 = __ldg(T + xp1 + yp0 + zp1);
    uint2 c110 = __ldg(T + xp1 + yp1 + zp0);
    uint2 c111 = __ldg(T + xp1 + yp1 + zp1);

    float u0 = 1.0f - tx, u1 = tx;
    float v0 = 1.0f - ty, v1 = ty;
    float s0 = 1.0f - tz, s1 = tz;

    float w000 = u0 * v0 * s0;
    float w001 = u0 * v0 * s1;
    float w010 = u0 * v1 * s0;
    float w011 = u0 * v1 * s1;
    float w100 = u1 * v0 * s0;
    float w101 = u1 * v0 * s1;
    float w110 = u1 * v1 * s0;
    float w111 = u1 * v1 * s1;

    float inv = 1.0f - m;   // weights sum to 1

    float Nx = inv, Ny = inv, Nz = inv;
    corner_acc(c000, w000, Nx, Ny, Nz);
    corner_acc(c001, w001, Nx, Ny, Nz);
    corner_acc(c010, w010, Nx, Ny, Nz);
    corner_acc(c011, w011, Nx, Ny, Nz);
    corner_acc(c100, w100, Nx, Ny, Nz);
    corner_acc(c101, w101, Nx, Ny, Nz);
    corner_acc(c110, w110, Nx, Ny, Nz);
    corner_acc(c111, w111, Nx, Ny, Nz);

    __half2 h_zw = *reinterpret_cast<__half2*>(&c000.y);
    float gridx = __half2float(__high2half(h_zw)) * m;

    __stcs(out + p, make_float4(Nx, Ny, Nz, gridx));
}

extern "C" void kernel_launch(void* const* d_in, const int* in_sizes, int n_in,
                              void* d_out, int out_size) {
    const float* grid = (const float*)d_in[0];
    const int*   vidx = (const int*)d_in[1];
    const float* pos  = (const float*)d_in[2];
    // d_in[3] = voxel_min_point: unused (recomputed bit-identically)
    const int*   mask = (const int*)d_in[4];

    int npix = in_sizes[4];  // H*W

    precompute_normals_kernel<<<NVOX / 16 / 256, 256>>>(grid);

    int blocks = (npix + 255) / 256;
    gather_kernel<<<blocks, 256>>>(vidx, pos, mask, (float4*)d_out, npix);
}